// round 16
// baseline (speedup 1.0000x reference)
#include <cuda_runtime.h>
#include <cuda_bf16.h>
#include <math.h>
#include <stdint.h>

// Problem constants (B=4, S=2048, D=2048, H=16, Dh=128)
#define BB    4
#define SS    2048
#define DD    2048
#define HH    16
#define DH    128
#define MM    (BB * SS)        // 8192 rows
#define NQKV  (3 * DD)         // 6144
#define GK    2048             // GEMM inner K

// ---------------------------------------------------------------------------
// Scratch: __device__ globals (allocation-guard-safe)
// ---------------------------------------------------------------------------
__device__ __nv_bfloat16  g_Xnb[(size_t)MM * DD];      // LN out bf16
__device__ __nv_bfloat16  g_Wt [(size_t)NQKV * DD];    // W_in^T  [6144][2048]
__device__ __nv_bfloat16  g_WoT[(size_t)DD * DD];      // W_out^T [2048][2048]
__device__ __nv_bfloat16  g_Qb [(size_t)BB * HH * SS * DH];  // Q roped+scaled [b][h][s][d]
__device__ __nv_bfloat16  g_Kb [(size_t)BB * HH * SS * DH];  // K roped       [b][h][s][d]
__device__ __nv_bfloat16  g_Vst[(size_t)MM * DD];      // V [row][h*Dh+d] (natural layout)
__device__ __nv_bfloat16  g_ctx[(size_t)MM * DD];      // attention ctx [row][d]

// ---------------------------------------------------------------------------
// PTX helpers (base-ISA sm_80+, legal on plain sm_103)
// ---------------------------------------------------------------------------
#define MMA16816(c, a, b_) \
    asm volatile("mma.sync.aligned.m16n8k16.row.col.f32.bf16.bf16.f32 " \
        "{%0,%1,%2,%3}, {%4,%5,%6,%7}, {%8,%9}, {%0,%1,%2,%3};" \
        : "+f"((c)[0]), "+f"((c)[1]), "+f"((c)[2]), "+f"((c)[3]) \
        : "r"((a)[0]), "r"((a)[1]), "r"((a)[2]), "r"((a)[3]), \
          "r"((b_)[0]), "r"((b_)[1]))

#define LDSM4(r, addr) \
    asm volatile("ldmatrix.sync.aligned.m8n8.x4.shared.b16 {%0,%1,%2,%3}, [%4];" \
        : "=r"((r)[0]), "=r"((r)[1]), "=r"((r)[2]), "=r"((r)[3]) : "r"(addr))

#define LDSM4T(r, addr) \
    asm volatile("ldmatrix.sync.aligned.m8n8.x4.trans.shared.b16 {%0,%1,%2,%3}, [%4];" \
        : "=r"((r)[0]), "=r"((r)[1]), "=r"((r)[2]), "=r"((r)[3]) : "r"(addr))

#define CP_ASYNC16(dst, src) \
    asm volatile("cp.async.cg.shared.global [%0], [%1], 16;" :: "r"(dst), "l"(src))
#define CP_COMMIT()  asm volatile("cp.async.commit_group;")
#define CP_WAIT0()   asm volatile("cp.async.wait_group 0;")

__device__ __forceinline__ uint32_t pack_bf16x2(float lo, float hi) {
    uint32_t r;
    asm("cvt.rn.bf16x2.f32 %0, %1, %2;" : "=r"(r) : "f"(hi), "f"(lo));
    return r;
}

// fast 2^y for y <= 0 (poly deg-5, rel err ~8e-5), FFMA-pipe only
__device__ __forceinline__ float exp2_fast(float y) {
    y = fmaxf(y, -60.f);
    float fl = floorf(y);
    float f  = y - fl;
    float p  = fmaf(f, 0.0013333558f, 0.0096181291f);
    p = fmaf(f, p, 0.0555041087f);
    p = fmaf(f, p, 0.2402265069f);
    p = fmaf(f, p, 0.6931471806f);
    p = fmaf(f, p, 1.0f);
    return __int_as_float(__float_as_int(p) + (((int)fl) << 23));
}

// ---------------------------------------------------------------------------
// Kernel 1: LayerNorm -> bf16
// ---------------------------------------------------------------------------
__global__ void __launch_bounds__(256) ln_kernel(
    const float* __restrict__ X, const float* __restrict__ w,
    const float* __restrict__ b, __nv_bfloat16* __restrict__ Xn)
{
    const int row = blockIdx.x;
    const int t   = threadIdx.x;
    const float4* xr = (const float4*)(X + (size_t)row * DD);

    float4 v0 = xr[t];
    float4 v1 = xr[t + 256];

    float s  = v0.x + v0.y + v0.z + v0.w + v1.x + v1.y + v1.z + v1.w;
    float sq = v0.x*v0.x + v0.y*v0.y + v0.z*v0.z + v0.w*v0.w
             + v1.x*v1.x + v1.y*v1.y + v1.z*v1.z + v1.w*v1.w;

    #pragma unroll
    for (int off = 16; off > 0; off >>= 1) {
        s  += __shfl_xor_sync(0xffffffffu, s,  off);
        sq += __shfl_xor_sync(0xffffffffu, sq, off);
    }
    __shared__ float sm[8], sm2[8];
    const int warp = t >> 5, lane = t & 31;
    if (lane == 0) { sm[warp] = s; sm2[warp] = sq; }
    __syncthreads();
    float S = 0.f, SQ = 0.f;
    #pragma unroll
    for (int i = 0; i < 8; i++) { S += sm[i]; SQ += sm2[i]; }

    const float mu  = S * (1.f / (float)DD);
    const float var = SQ * (1.f / (float)DD) - mu * mu;
    const float inv = rsqrtf(var + 1e-5f);

    const float4* wv = (const float4*)w;
    const float4* bv = (const float4*)b;
    float4 w0 = wv[t], w1 = wv[t + 256];
    float4 b0 = bv[t], b1 = bv[t + 256];

    __nv_bfloat16* H = Xn + (size_t)row * DD;
    H[t*4+0] = __float2bfloat16((v0.x - mu) * inv * w0.x + b0.x);
    H[t*4+1] = __float2bfloat16((v0.y - mu) * inv * w0.y + b0.y);
    H[t*4+2] = __float2bfloat16((v0.z - mu) * inv * w0.z + b0.z);
    H[t*4+3] = __float2bfloat16((v0.w - mu) * inv * w0.w + b0.w);
    H[(t+256)*4+0] = __float2bfloat16((v1.x - mu) * inv * w1.x + b1.x);
    H[(t+256)*4+1] = __float2bfloat16((v1.y - mu) * inv * w1.y + b1.y);
    H[(t+256)*4+2] = __float2bfloat16((v1.z - mu) * inv * w1.z + b1.z);
    H[(t+256)*4+3] = __float2bfloat16((v1.w - mu) * inv * w1.w + b1.w);
}

// ---------------------------------------------------------------------------
// Kernel 2: weight transpose -> bf16.  W[2048][Ncols] fp32 -> Wt[Ncols][2048]
// ---------------------------------------------------------------------------
__global__ void __launch_bounds__(256) wsplit_kernel(
    const float* __restrict__ W, __nv_bfloat16* __restrict__ Wt, int Ncols)
{
    __shared__ float ts[32][33];
    const int tx = threadIdx.x & 31, ty = threadIdx.x >> 5;   // 32x8
    const int n0 = blockIdx.x * 32, k0 = blockIdx.y * 32;

    #pragma unroll
    for (int j = 0; j < 4; j++) {
        int r = ty + j * 8;
        ts[r][tx] = W[(size_t)(k0 + r) * Ncols + n0 + tx];
    }
    __syncthreads();
    #pragma unroll
    for (int j = 0; j < 4; j++) {
        int r = ty + j * 8;
        Wt[(size_t)(n0 + r) * GK + k0 + tx] = __float2bfloat16(ts[tx][r]);
    }
}

// ---------------------------------------------------------------------------
// GEMM core.  Tile 128x128, BK=64, 4 warps x (64x64), cp.async double buffer.
// ---------------------------------------------------------------------------
#define BK    64
#define ASTR  72                       // 144B rows = 9x16B odd -> conflict-free ldmatrix
#define NCH   32                       // 2048 / 64
#define TILE_E (128 * ASTR)            // bf16 elems per tile buffer
#define GEMM_SMEM (4 * TILE_E * 2)     // bytes

#define GEMM_PROLOG() \
    extern __shared__ __nv_bfloat16 gsm[]; \
    __nv_bfloat16* Asb = gsm; \
    __nv_bfloat16* Bsb = gsm + 2 * TILE_E; \
    const int tid  = threadIdx.x; \
    const int wid  = tid >> 5, lane = tid & 31; \
    const int gid  = lane >> 2, tid2 = lane & 3; \
    const int wm   = wid & 1; \
    const int wn   = wid >> 1; \
    const int bm   = blockIdx.y * 128, bn = blockIdx.x * 128; \
    float acc[4][8][4]; \
    _Pragma("unroll") \
    for (int i = 0; i < 4; i++) \
        _Pragma("unroll") \
        for (int j = 0; j < 8; j++) \
            _Pragma("unroll") \
            for (int q = 0; q < 4; q++) acc[i][j][q] = 0.f; \
    const int a_row = wm * 64 + ((lane >> 3) & 1) * 8 + (lane & 7); \
    const int a_k   = (lane >> 4) * 8; \
    const int b_row = wn * 64 + ((lane >> 4) & 1) * 8 + (lane & 7); \
    const int b_k   = ((lane >> 3) & 1) * 8;

#define LOAD_TILES(buf, koff) do { \
    _Pragma("unroll") \
    for (int u = 0; u < 8; u++) { \
        int f = tid + u * 128; \
        int r = f >> 3, cb = (f & 7) * 8; \
        uint32_t da = (uint32_t)__cvta_generic_to_shared(&Asb[(buf) * TILE_E + r * ASTR + cb]); \
        CP_ASYNC16(da, A + (size_t)(bm + r) * GK + (koff) + cb); \
        uint32_t db = (uint32_t)__cvta_generic_to_shared(&Bsb[(buf) * TILE_E + r * ASTR + cb]); \
        CP_ASYNC16(db, B + (size_t)(bn + r) * GK + (koff) + cb); \
    } \
    CP_COMMIT(); \
} while (0)

#define GEMM_MAINLOOP() \
    LOAD_TILES(0, 0); \
    CP_WAIT0(); \
    __syncthreads(); \
    for (int kc = 0; kc < NCH; kc++) { \
        const int cur = kc & 1; \
        if (kc + 1 < NCH) LOAD_TILES((kc + 1) & 1, (kc + 1) * BK); \
        const __nv_bfloat16* Acur = Asb + cur * TILE_E; \
        const __nv_bfloat16* Bcur = Bsb + cur * TILE_E; \
        _Pragma("unroll") \
        for (int ks = 0; ks < BK; ks += 16) { \
            uint32_t af[4][4], bf_[8][2]; \
            _Pragma("unroll") \
            for (int mf = 0; mf < 4; mf++) { \
                uint32_t addr = (uint32_t)__cvta_generic_to_shared( \
                    (void*)&Acur[(a_row + mf * 16) * ASTR + ks + a_k]); \
                LDSM4(af[mf], addr); \
            } \
            _Pragma("unroll") \
            for (int np = 0; np < 4; np++) { \
                uint32_t r4[4]; \
                uint32_t addr = (uint32_t)__cvta_generic_to_shared( \
                    (void*)&Bcur[(b_row + np * 16) * ASTR + ks + b_k]); \
                LDSM4(r4, addr); \
                bf_[2*np][0]   = r4[0]; bf_[2*np][1]   = r4[1]; \
                bf_[2*np+1][0] = r4[2]; bf_[2*np+1][1] = r4[3]; \
            } \
            _Pragma("unroll") \
            for (int mf = 0; mf < 4; mf++) \
                _Pragma("unroll") \
                for (int nf = 0; nf < 8; nf++) \
                    MMA16816(acc[mf][nf], af[mf], bf_[nf]); \
        } \
        if (kc + 1 < NCH) CP_WAIT0(); \
        __syncthreads(); \
    }

// ---------------------------------------------------------------------------
// Kernel 3a: QKV GEMM with fused RoPE + bf16 conversion epilogue (MUFU math).
// ---------------------------------------------------------------------------
__global__ void __launch_bounds__(128, 2) mma_gemm_qkv(
    const __nv_bfloat16* __restrict__ A, const __nv_bfloat16* __restrict__ B,
    __nv_bfloat16* __restrict__ Qb, __nv_bfloat16* __restrict__ Kb,
    __nv_bfloat16* __restrict__ Vst)
{
    GEMM_PROLOG();
    GEMM_MAINLOOP();

    const float qs = 0.08838834764831845f * 1.4426950408889634f;

    #pragma unroll
    for (int nf = 0; nf < 8; nf++) {
        const int col  = bn + wn * 64 + nf * 8 + tid2 * 2;
        const int sec  = col >> 11;               // uniform per block
        const int rr   = col & 2047;
        const int head = rr >> 7;                 // uniform per block
        const int dcol = rr & 127;
        const bool rot = (dcol < 64);
        float invf = 0.f;
        if (rot)
            invf = __expf(-9.210340371976184f * ((float)(dcol >> 1) * (1.f / 32.f)));

        #pragma unroll
        for (int mf = 0; mf < 4; mf++) {
            #pragma unroll
            for (int half = 0; half < 2; half++) {
                const int row = bm + wm * 64 + mf * 16 + gid + half * 8;
                const int s   = row & (SS - 1);
                const int b   = row >> 11;
                float x1 = acc[mf][nf][half * 2];
                float x2 = acc[mf][nf][half * 2 + 1];

                if (sec < 2) {
                    if (rot) {
                        float sn, cs;
                        __sincosf((float)s * invf, &sn, &cs);
                        float r1 = x1 * cs - x2 * sn;
                        float r2 = x2 * cs + x1 * sn;
                        x1 = r1; x2 = r2;
                    }
                    if (sec == 0) { x1 *= qs; x2 *= qs; }
                    __nv_bfloat16* dst = (sec == 0) ? Qb : Kb;
                    *(uint32_t*)(dst + (((size_t)b * HH + head) * SS + s) * DH + dcol)
                        = pack_bf16x2(x1, x2);
                } else {
                    *(uint32_t*)(Vst + (size_t)row * DD + head * DH + dcol)
                        = pack_bf16x2(x1, x2);
                }
            }
        }
    }
}

// ---------------------------------------------------------------------------
// Kernel 3b: plain GEMM + residual (out projection), fp32 output.
// ---------------------------------------------------------------------------
__global__ void __launch_bounds__(128, 2) mma_gemm_out(
    const __nv_bfloat16* __restrict__ A, const __nv_bfloat16* __restrict__ B,
    const float* __restrict__ R, float* __restrict__ C, int N)
{
    GEMM_PROLOG();
    GEMM_MAINLOOP();

    #pragma unroll
    for (int mf = 0; mf < 4; mf++) {
        #pragma unroll
        for (int nf = 0; nf < 8; nf++) {
            const int row = bm + wm * 64 + mf * 16 + gid;
            const int col = bn + wn * 64 + nf * 8 + tid2 * 2;
            size_t o0 = (size_t)row * N + col;
            size_t o1 = (size_t)(row + 8) * N + col;
            float2 v0 = make_float2(acc[mf][nf][0], acc[mf][nf][1]);
            float2 v1 = make_float2(acc[mf][nf][2], acc[mf][nf][3]);
            float2 q0 = *(const float2*)(R + o0);
            float2 q1 = *(const float2*)(R + o1);
            v0.x += q0.x; v0.y += q0.y;
            v1.x += q1.x; v1.y += q1.y;
            *(float2*)(C + o0) = v0;
            *(float2*)(C + o1) = v1;
        }
    }
}

// ---------------------------------------------------------------------------
// Kernel 4: flash attention on mma.sync (R13 geometry: 64 q-rows, 128 thr).
// K from Kb [s][d]; V directly from Vst [s][h*Dh+d] via ldmatrix.trans
// (no pre-transpose kernel). cp.async double buffer.
// Both tiles 64 rows x 136-stride. Dyn smem: 2 x 2 x 64*136 x 2B = 69632 B.
// ---------------------------------------------------------------------------
#define AST 136
#define ATTN_TILE (64 * AST)
#define ATTN_SMEM (4 * ATTN_TILE * 2)

__global__ void __launch_bounds__(128, 2) attn_mma(
    const __nv_bfloat16* __restrict__ Qb, const __nv_bfloat16* __restrict__ Kb,
    const __nv_bfloat16* __restrict__ Vst, __nv_bfloat16* __restrict__ ctx)
{
    extern __shared__ __nv_bfloat16 dsm[];
    __nv_bfloat16* KsBase = dsm;                   // 2 x 64*AST
    __nv_bfloat16* VsBase = dsm + 2 * ATTN_TILE;   // 2 x 64*AST ([s][d] layout)

    const int tid = threadIdx.x, w = tid >> 5, lane = tid & 31;
    const int gid = lane >> 2, tid2 = lane & 3;
    const int qt = blockIdx.x, h = blockIdx.y, b = blockIdx.z;
    const int bh = b * HH + h;

    // ldmatrix lane mapping: non-trans (K) and trans (V)
    const int bl_row = ((lane >> 4) & 1) * 8 + (lane & 7);   // K: n-row within 16
    const int bl_k   = ((lane >> 3) & 1) * 8;                // K: k offset
    const int vl_s   = ((lane >> 3) & 1) * 8 + (lane & 7);   // V: s-row within 16
    const int vl_d   = ((lane >> 4) & 1) * 8;                // V: d offset

    const __nv_bfloat16* kgp = Kb  + (size_t)bh * SS * DH;
    const __nv_bfloat16* vgp = Vst + (size_t)(b * SS) * DD + h * DH;

    #define ATTN_LOAD(buf, kt_) do { \
        __nv_bfloat16* Kd = KsBase + (buf) * ATTN_TILE; \
        __nv_bfloat16* Vd = VsBase + (buf) * ATTN_TILE; \
        _Pragma("unroll") \
        for (int u = 0; u < 8; u++) { \
            int f = tid + u * 128; \
            int r = f >> 4, c = (f & 15) * 8; \
            uint32_t dk = (uint32_t)__cvta_generic_to_shared(&Kd[r * AST + c]); \
            CP_ASYNC16(dk, kgp + (size_t)((kt_) * 64 + r) * DH + c); \
            uint32_t dv = (uint32_t)__cvta_generic_to_shared(&Vd[r * AST + c]); \
            CP_ASYNC16(dv, vgp + (size_t)((kt_) * 64 + r) * DD + c); \
        } \
        CP_COMMIT(); \
    } while (0)

    // Q fragments: 8 k-frags x 4 regs; warp w owns q-rows qt*64 + w*16 ..
    uint32_t qf[8][4];
    {
        const __nv_bfloat16* qp =
            Qb + ((size_t)bh * SS + qt * 64 + w * 16) * DH;
        #pragma unroll
        for (int kf = 0; kf < 8; kf++) {
            const __nv_bfloat16* p = qp + kf * 16 + tid2 * 2;
            qf[kf][0] = *(const uint32_t*)(p + (size_t)gid * DH);
            qf[kf][1] = *(const uint32_t*)(p + (size_t)(gid + 8) * DH);
            qf[kf][2] = *(const uint32_t*)(p + (size_t)gid * DH + 8);
            qf[kf][3] = *(const uint32_t*)(p + (size_t)(gid + 8) * DH + 8);
        }
    }

    float o[16][4];
    #pragma unroll
    for (int i = 0; i < 16; i++)
        #pragma unroll
        for (int q = 0; q < 4; q++) o[i][q] = 0.f;
    float m0 = -1e30f, m1 = -1e30f, l0 = 0.f, l1 = 0.f;

    ATTN_LOAD(0, 0);
    CP_WAIT0();
    __syncthreads();

    for (int kt = 0; kt < SS / 64; kt++) {
        const int cur = kt & 1;
        if (kt + 1 < SS / 64) ATTN_LOAD((kt + 1) & 1, kt + 1);

        const __nv_bfloat16* Ks = KsBase + cur * ATTN_TILE;
        const __nv_bfloat16* Vs = VsBase + cur * ATTN_TILE;

        // scores S[16 x 64] via ldmatrix B-frags
        float s[8][4];
        #pragma unroll
        for (int nf = 0; nf < 8; nf++)
            #pragma unroll
            for (int q = 0; q < 4; q++) s[nf][q] = 0.f;

        #pragma unroll
        for (int kf = 0; kf < 8; kf++) {
            #pragma unroll
            for (int np = 0; np < 4; np++) {
                uint32_t r4[4];
                uint32_t addr = (uint32_t)__cvta_generic_to_shared(
                    (void*)&Ks[(np * 16 + bl_row) * AST + kf * 16 + bl_k]);
                LDSM4(r4, addr);
                MMA16816(s[2*np],     qf[kf], r4);
                MMA16816(s[2*np + 1], qf[kf], r4 + 2);
            }
        }

        // online softmax (rows gid -> m0/l0, gid+8 -> m1/l1)
        float mx0 = -1e30f, mx1 = -1e30f;
        #pragma unroll
        for (int nf = 0; nf < 8; nf++) {
            mx0 = fmaxf(mx0, fmaxf(s[nf][0], s[nf][1]));
            mx1 = fmaxf(mx1, fmaxf(s[nf][2], s[nf][3]));
        }
        mx0 = fmaxf(mx0, __shfl_xor_sync(0xffffffffu, mx0, 1));
        mx0 = fmaxf(mx0, __shfl_xor_sync(0xffffffffu, mx0, 2));
        mx1 = fmaxf(mx1, __shfl_xor_sync(0xffffffffu, mx1, 1));
        mx1 = fmaxf(mx1, __shfl_xor_sync(0xffffffffu, mx1, 2));

        float nm0 = fmaxf(m0, mx0), nm1 = fmaxf(m1, mx1);
        float f0 = exp2_fast(m0 - nm0), f1 = exp2_fast(m1 - nm1);
        m0 = nm0; m1 = nm1;

        float sum0 = 0.f, sum1 = 0.f;
        #pragma unroll
        for (int nf = 0; nf < 8; nf++) {
            s[nf][0] = exp2_fast(s[nf][0] - m0);
            s[nf][1] = exp2_fast(s[nf][1] - m0);
            s[nf][2] = exp2_fast(s[nf][2] - m1);
            s[nf][3] = exp2_fast(s[nf][3] - m1);
            sum0 += s[nf][0] + s[nf][1];
            sum1 += s[nf][2] + s[nf][3];
        }
        sum0 += __shfl_xor_sync(0xffffffffu, sum0, 1);
        sum0 += __shfl_xor_sync(0xffffffffu, sum0, 2);
        sum1 += __shfl_xor_sync(0xffffffffu, sum1, 1);
        sum1 += __shfl_xor_sync(0xffffffffu, sum1, 2);
        l0 = l0 * f0 + sum0;
        l1 = l1 * f1 + sum1;

        #pragma unroll
        for (int nd = 0; nd < 16; nd++) {
            o[nd][0] *= f0; o[nd][1] *= f0;
            o[nd][2] *= f1; o[nd][3] *= f1;
        }

        // P @ V via ldmatrix.trans from [s][d] tile
        #pragma unroll
        for (int kf2 = 0; kf2 < 4; kf2++) {
            uint32_t pa[4];
            pa[0] = pack_bf16x2(s[2*kf2][0],   s[2*kf2][1]);
            pa[1] = pack_bf16x2(s[2*kf2][2],   s[2*kf2][3]);
            pa[2] = pack_bf16x2(s[2*kf2+1][0], s[2*kf2+1][1]);
            pa[3] = pack_bf16x2(s[2*kf2+1][2], s[2*kf2+1][3]);
            #pragma unroll
            for (int np2 = 0; np2 < 8; np2++) {
                uint32_t r4[4];
                uint32_t addr = (uint32_t)__cvta_generic_to_shared(
                    (void*)&Vs[(kf2 * 16 + vl_s) * AST + np2 * 16 + vl_d]);
                LDSM4T(r4, addr);
                MMA16816(o[2*np2],     pa, r4);
                MMA16816(o[2*np2 + 1], pa, r4 + 2);
            }
        }

        if (kt + 1 < SS / 64) CP_WAIT0();
        __syncthreads();
    }

    // epilogue: normalize, write ctx [row][h*128+d] bf16
    const float il0 = 1.f / l0, il1 = 1.f / l1;
    const size_t row0 = (size_t)(b * SS + qt * 64 + w * 16 + gid);
    __nv_bfloat16* cp0 = ctx + row0 * DD + h * DH + tid2 * 2;
    __nv_bfloat16* cp1 = cp0 + 8 * DD;
    #pragma unroll
    for (int nd = 0; nd < 16; nd++) {
        *(uint32_t*)(cp0 + nd * 8) = pack_bf16x2(o[nd][0] * il0, o[nd][1] * il0);
        *(uint32_t*)(cp1 + nd * 8) = pack_bf16x2(o[nd][2] * il1, o[nd][3] * il1);
    }
    #undef ATTN_LOAD
}

// ---------------------------------------------------------------------------
// Launch. Inputs: X, ln_w, ln_b, W_in, W_out. Output fp32.
// ---------------------------------------------------------------------------
extern "C" void kernel_launch(void* const* d_in, const int* in_sizes, int n_in,
                              void* d_out, int out_size)
{
    const float* X     = (const float*)d_in[0];
    const float* ln_w  = (const float*)d_in[1];
    const float* ln_b  = (const float*)d_in[2];
    const float* W_in  = (const float*)d_in[3];
    const float* W_out = (const float*)d_in[4];
    float*       out   = (float*)d_out;

    __nv_bfloat16 *pXn, *pWt, *pWoT, *pQb, *pKb, *pVst, *pCtx;
    cudaGetSymbolAddress((void**)&pXn,  g_Xnb);
    cudaGetSymbolAddress((void**)&pWt,  g_Wt);
    cudaGetSymbolAddress((void**)&pWoT, g_WoT);
    cudaGetSymbolAddress((void**)&pQb,  g_Qb);
    cudaGetSymbolAddress((void**)&pKb,  g_Kb);
    cudaGetSymbolAddress((void**)&pVst, g_Vst);
    cudaGetSymbolAddress((void**)&pCtx, g_ctx);

    cudaFuncSetAttribute(attn_mma,
        cudaFuncAttributeMaxDynamicSharedMemorySize, ATTN_SMEM);
    cudaFuncSetAttribute(mma_gemm_qkv,
        cudaFuncAttributeMaxDynamicSharedMemorySize, GEMM_SMEM);
    cudaFuncSetAttribute(mma_gemm_out,
        cudaFuncAttributeMaxDynamicSharedMemorySize, GEMM_SMEM);

    // 0) Weight transpose -> bf16
    wsplit_kernel<<<dim3(NQKV / 32, DD / 32), 256>>>(W_in,  pWt,  NQKV);
    wsplit_kernel<<<dim3(DD   / 32, DD / 32), 256>>>(W_out, pWoT, DD);

    // 1) LayerNorm -> bf16
    ln_kernel<<<MM, 256>>>(X, ln_w, ln_b, pXn);

    // 2) QKV projection with fused RoPE + bf16 conversion (BK=64)
    mma_gemm_qkv<<<dim3(NQKV / 128, MM / 128), 128, GEMM_SMEM>>>(
        pXn, pWt, pQb, pKb, pVst);

    // 3) Attention (64-q-row blocks; V direct from Vst via ldmatrix.trans)
    attn_mma<<<dim3(SS / 64, HH, BB), 128, ATTN_SMEM>>>(pQb, pKb, pVst, pCtx);

    // 4) Output projection + residual (BK=64)
    mma_gemm_out<<<dim3(DD / 128, MM / 128), 128, GEMM_SMEM>>>(
        pCtx, pWoT, X, out, DD);
}

// round 17
// speedup vs baseline: 1.4823x; 1.4823x over previous
#include <cuda_runtime.h>
#include <cuda_bf16.h>
#include <math.h>
#include <stdint.h>

// Problem constants (B=4, S=2048, D=2048, H=16, Dh=128)
#define BB    4
#define SS    2048
#define DD    2048
#define HH    16
#define DH    128
#define MM    (BB * SS)        // 8192 rows
#define NQKV  (3 * DD)         // 6144
#define GK    2048             // GEMM inner K

// ---------------------------------------------------------------------------
// Scratch: __device__ globals (allocation-guard-safe)
// ---------------------------------------------------------------------------
__device__ __nv_bfloat16  g_Xnb[(size_t)MM * DD];      // LN out bf16
__device__ __nv_bfloat16  g_Wt [(size_t)NQKV * DD];    // W_in^T  [6144][2048]
__device__ __nv_bfloat16  g_WoT[(size_t)DD * DD];      // W_out^T [2048][2048]
__device__ __nv_bfloat16  g_Qb [(size_t)BB * HH * SS * DH];  // Q roped+scaled [b][h][s][d]
__device__ __nv_bfloat16  g_Kb [(size_t)BB * HH * SS * DH];  // K roped       [b][h][s][d]
__device__ __nv_bfloat16  g_Vst[(size_t)MM * DD];      // V staging [row][h*Dh+d]
__device__ __nv_bfloat16  g_Vt [(size_t)BB * HH * DH * SS];  // V transposed [b][h][d][s]
__device__ __nv_bfloat16  g_ctx[(size_t)MM * DD];      // attention ctx [row][d]

// ---------------------------------------------------------------------------
// PTX helpers (base-ISA sm_80+, legal on plain sm_103)
// ---------------------------------------------------------------------------
#define MMA16816(c, a, b_) \
    asm volatile("mma.sync.aligned.m16n8k16.row.col.f32.bf16.bf16.f32 " \
        "{%0,%1,%2,%3}, {%4,%5,%6,%7}, {%8,%9}, {%0,%1,%2,%3};" \
        : "+f"((c)[0]), "+f"((c)[1]), "+f"((c)[2]), "+f"((c)[3]) \
        : "r"((a)[0]), "r"((a)[1]), "r"((a)[2]), "r"((a)[3]), \
          "r"((b_)[0]), "r"((b_)[1]))

#define LDSM4(r, addr) \
    asm volatile("ldmatrix.sync.aligned.m8n8.x4.shared.b16 {%0,%1,%2,%3}, [%4];" \
        : "=r"((r)[0]), "=r"((r)[1]), "=r"((r)[2]), "=r"((r)[3]) : "r"(addr))

#define CP_ASYNC16(dst, src) \
    asm volatile("cp.async.cg.shared.global [%0], [%1], 16;" :: "r"(dst), "l"(src))
#define CP_COMMIT()  asm volatile("cp.async.commit_group;")
#define CP_WAIT0()   asm volatile("cp.async.wait_group 0;")
#define CP_WAIT1()   asm volatile("cp.async.wait_group 1;")

__device__ __forceinline__ uint32_t pack_bf16x2(float lo, float hi) {
    uint32_t r;
    asm("cvt.rn.bf16x2.f32 %0, %1, %2;" : "=r"(r) : "f"(hi), "f"(lo));
    return r;
}

// fast 2^y for y <= 0 (poly deg-5, rel err ~8e-5), FFMA-pipe only
__device__ __forceinline__ float exp2_fast(float y) {
    y = fmaxf(y, -60.f);
    float fl = floorf(y);
    float f  = y - fl;
    float p  = fmaf(f, 0.0013333558f, 0.0096181291f);
    p = fmaf(f, p, 0.0555041087f);
    p = fmaf(f, p, 0.2402265069f);
    p = fmaf(f, p, 0.6931471806f);
    p = fmaf(f, p, 1.0f);
    return __int_as_float(__float_as_int(p) + (((int)fl) << 23));
}

// ---------------------------------------------------------------------------
// Kernel 1: LayerNorm -> bf16
// ---------------------------------------------------------------------------
__global__ void __launch_bounds__(256) ln_kernel(
    const float* __restrict__ X, const float* __restrict__ w,
    const float* __restrict__ b, __nv_bfloat16* __restrict__ Xn)
{
    const int row = blockIdx.x;
    const int t   = threadIdx.x;
    const float4* xr = (const float4*)(X + (size_t)row * DD);

    float4 v0 = xr[t];
    float4 v1 = xr[t + 256];

    float s  = v0.x + v0.y + v0.z + v0.w + v1.x + v1.y + v1.z + v1.w;
    float sq = v0.x*v0.x + v0.y*v0.y + v0.z*v0.z + v0.w*v0.w
             + v1.x*v1.x + v1.y*v1.y + v1.z*v1.z + v1.w*v1.w;

    #pragma unroll
    for (int off = 16; off > 0; off >>= 1) {
        s  += __shfl_xor_sync(0xffffffffu, s,  off);
        sq += __shfl_xor_sync(0xffffffffu, sq, off);
    }
    __shared__ float sm[8], sm2[8];
    const int warp = t >> 5, lane = t & 31;
    if (lane == 0) { sm[warp] = s; sm2[warp] = sq; }
    __syncthreads();
    float S = 0.f, SQ = 0.f;
    #pragma unroll
    for (int i = 0; i < 8; i++) { S += sm[i]; SQ += sm2[i]; }

    const float mu  = S * (1.f / (float)DD);
    const float var = SQ * (1.f / (float)DD) - mu * mu;
    const float inv = rsqrtf(var + 1e-5f);

    const float4* wv = (const float4*)w;
    const float4* bv = (const float4*)b;
    float4 w0 = wv[t], w1 = wv[t + 256];
    float4 b0 = bv[t], b1 = bv[t + 256];

    __nv_bfloat16* H = Xn + (size_t)row * DD;
    H[t*4+0] = __float2bfloat16((v0.x - mu) * inv * w0.x + b0.x);
    H[t*4+1] = __float2bfloat16((v0.y - mu) * inv * w0.y + b0.y);
    H[t*4+2] = __float2bfloat16((v0.z - mu) * inv * w0.z + b0.z);
    H[t*4+3] = __float2bfloat16((v0.w - mu) * inv * w0.w + b0.w);
    H[(t+256)*4+0] = __float2bfloat16((v1.x - mu) * inv * w1.x + b1.x);
    H[(t+256)*4+1] = __float2bfloat16((v1.y - mu) * inv * w1.y + b1.y);
    H[(t+256)*4+2] = __float2bfloat16((v1.z - mu) * inv * w1.z + b1.z);
    H[(t+256)*4+3] = __float2bfloat16((v1.w - mu) * inv * w1.w + b1.w);
}

// ---------------------------------------------------------------------------
// Kernel 2: weight transpose -> bf16.  W[2048][Ncols] fp32 -> Wt[Ncols][2048]
// ---------------------------------------------------------------------------
__global__ void __launch_bounds__(256) wsplit_kernel(
    const float* __restrict__ W, __nv_bfloat16* __restrict__ Wt, int Ncols)
{
    __shared__ float ts[32][33];
    const int tx = threadIdx.x & 31, ty = threadIdx.x >> 5;   // 32x8
    const int n0 = blockIdx.x * 32, k0 = blockIdx.y * 32;

    #pragma unroll
    for (int j = 0; j < 4; j++) {
        int r = ty + j * 8;
        ts[r][tx] = W[(size_t)(k0 + r) * Ncols + n0 + tx];
    }
    __syncthreads();
    #pragma unroll
    for (int j = 0; j < 4; j++) {
        int r = ty + j * 8;
        Wt[(size_t)(n0 + r) * GK + k0 + tx] = __float2bfloat16(ts[tx][r]);
    }
}

// ---------------------------------------------------------------------------
// GEMM core.  Tile 128x128, BK=64, 4 warps x (64x64), cp.async 3-stage.
// Dyn smem: 3 stages x (A+B tiles, 36864 B) = 110592 B. 2 CTAs/SM fit.
// ---------------------------------------------------------------------------
#define BK    64
#define ASTR  72                       // 144B rows = 9x16B odd -> conflict-free ldmatrix
#define NCH   32                       // 2048 / 64
#define TILE_E (128 * ASTR)            // bf16 elems per tile buffer
#define GEMM_SMEM (6 * TILE_E * 2)     // 3 stages x (A + B) bytes

#define GEMM_PROLOG() \
    extern __shared__ __nv_bfloat16 gsm[]; \
    __nv_bfloat16* Asb = gsm; \
    __nv_bfloat16* Bsb = gsm + 3 * TILE_E; \
    const int tid  = threadIdx.x; \
    const int wid  = tid >> 5, lane = tid & 31; \
    const int gid  = lane >> 2, tid2 = lane & 3; \
    const int wm   = wid & 1; \
    const int wn   = wid >> 1; \
    const int bm   = blockIdx.y * 128, bn = blockIdx.x * 128; \
    float acc[4][8][4]; \
    _Pragma("unroll") \
    for (int i = 0; i < 4; i++) \
        _Pragma("unroll") \
        for (int j = 0; j < 8; j++) \
            _Pragma("unroll") \
            for (int q = 0; q < 4; q++) acc[i][j][q] = 0.f; \
    const int a_row = wm * 64 + ((lane >> 3) & 1) * 8 + (lane & 7); \
    const int a_k   = (lane >> 4) * 8; \
    const int b_row = wn * 64 + ((lane >> 4) & 1) * 8 + (lane & 7); \
    const int b_k   = ((lane >> 3) & 1) * 8;

#define LOAD_TILES(buf, koff) do { \
    _Pragma("unroll") \
    for (int u = 0; u < 8; u++) { \
        int f = tid + u * 128; \
        int r = f >> 3, cb = (f & 7) * 8; \
        uint32_t da = (uint32_t)__cvta_generic_to_shared(&Asb[(buf) * TILE_E + r * ASTR + cb]); \
        CP_ASYNC16(da, A + (size_t)(bm + r) * GK + (koff) + cb); \
        uint32_t db = (uint32_t)__cvta_generic_to_shared(&Bsb[(buf) * TILE_E + r * ASTR + cb]); \
        CP_ASYNC16(db, B + (size_t)(bn + r) * GK + (koff) + cb); \
    } \
    CP_COMMIT(); \
} while (0)

// 3-stage pipeline: compute of chunk kc overlaps loads kc+1 and kc+2.
// Loop-head wait: group kc must be complete; kc+1 may stay in flight.
#define GEMM_MAINLOOP() \
    LOAD_TILES(0, 0); \
    LOAD_TILES(1, BK); \
    for (int kc = 0; kc < NCH; kc++) { \
        const int cur = kc % 3; \
        if (kc + 1 < NCH) { CP_WAIT1(); } else { CP_WAIT0(); } \
        __syncthreads(); \
        if (kc + 2 < NCH) LOAD_TILES((kc + 2) % 3, (kc + 2) * BK); \
        const __nv_bfloat16* Acur = Asb + cur * TILE_E; \
        const __nv_bfloat16* Bcur = Bsb + cur * TILE_E; \
        _Pragma("unroll") \
        for (int ks = 0; ks < BK; ks += 16) { \
            uint32_t af[4][4], bf_[8][2]; \
            _Pragma("unroll") \
            for (int mf = 0; mf < 4; mf++) { \
                uint32_t addr = (uint32_t)__cvta_generic_to_shared( \
                    (void*)&Acur[(a_row + mf * 16) * ASTR + ks + a_k]); \
                LDSM4(af[mf], addr); \
            } \
            _Pragma("unroll") \
            for (int np = 0; np < 4; np++) { \
                uint32_t r4[4]; \
                uint32_t addr = (uint32_t)__cvta_generic_to_shared( \
                    (void*)&Bcur[(b_row + np * 16) * ASTR + ks + b_k]); \
                LDSM4(r4, addr); \
                bf_[2*np][0]   = r4[0]; bf_[2*np][1]   = r4[1]; \
                bf_[2*np+1][0] = r4[2]; bf_[2*np+1][1] = r4[3]; \
            } \
            _Pragma("unroll") \
            for (int mf = 0; mf < 4; mf++) \
                _Pragma("unroll") \
                for (int nf = 0; nf < 8; nf++) \
                    MMA16816(acc[mf][nf], af[mf], bf_[nf]); \
        } \
    }

// ---------------------------------------------------------------------------
// Kernel 3a: QKV GEMM with fused RoPE + bf16 conversion epilogue (MUFU math).
// ---------------------------------------------------------------------------
__global__ void __launch_bounds__(128, 2) mma_gemm_qkv(
    const __nv_bfloat16* __restrict__ A, const __nv_bfloat16* __restrict__ B,
    __nv_bfloat16* __restrict__ Qb, __nv_bfloat16* __restrict__ Kb,
    __nv_bfloat16* __restrict__ Vst)
{
    GEMM_PROLOG();
    GEMM_MAINLOOP();

    const float qs = 0.08838834764831845f * 1.4426950408889634f;

    #pragma unroll
    for (int nf = 0; nf < 8; nf++) {
        const int col  = bn + wn * 64 + nf * 8 + tid2 * 2;
        const int sec  = col >> 11;               // uniform per block
        const int rr   = col & 2047;
        const int head = rr >> 7;                 // uniform per block
        const int dcol = rr & 127;
        const bool rot = (dcol < 64);
        float invf = 0.f;
        if (rot)
            invf = __expf(-9.210340371976184f * ((float)(dcol >> 1) * (1.f / 32.f)));

        #pragma unroll
        for (int mf = 0; mf < 4; mf++) {
            #pragma unroll
            for (int half = 0; half < 2; half++) {
                const int row = bm + wm * 64 + mf * 16 + gid + half * 8;
                const int s   = row & (SS - 1);
                const int b   = row >> 11;
                float x1 = acc[mf][nf][half * 2];
                float x2 = acc[mf][nf][half * 2 + 1];

                if (sec < 2) {
                    if (rot) {
                        float sn, cs;
                        __sincosf((float)s * invf, &sn, &cs);
                        float r1 = x1 * cs - x2 * sn;
                        float r2 = x2 * cs + x1 * sn;
                        x1 = r1; x2 = r2;
                    }
                    if (sec == 0) { x1 *= qs; x2 *= qs; }
                    __nv_bfloat16* dst = (sec == 0) ? Qb : Kb;
                    *(uint32_t*)(dst + (((size_t)b * HH + head) * SS + s) * DH + dcol)
                        = pack_bf16x2(x1, x2);
                } else {
                    *(uint32_t*)(Vst + (size_t)row * DD + head * DH + dcol)
                        = pack_bf16x2(x1, x2);
                }
            }
        }
    }
}

// ---------------------------------------------------------------------------
// Kernel 3b: plain GEMM + residual (out projection), fp32 output.
// ---------------------------------------------------------------------------
__global__ void __launch_bounds__(128, 2) mma_gemm_out(
    const __nv_bfloat16* __restrict__ A, const __nv_bfloat16* __restrict__ B,
    const float* __restrict__ R, float* __restrict__ C, int N)
{
    GEMM_PROLOG();
    GEMM_MAINLOOP();

    #pragma unroll
    for (int mf = 0; mf < 4; mf++) {
        #pragma unroll
        for (int nf = 0; nf < 8; nf++) {
            const int row = bm + wm * 64 + mf * 16 + gid;
            const int col = bn + wn * 64 + nf * 8 + tid2 * 2;
            size_t o0 = (size_t)row * N + col;
            size_t o1 = (size_t)(row + 8) * N + col;
            float2 v0 = make_float2(acc[mf][nf][0], acc[mf][nf][1]);
            float2 v1 = make_float2(acc[mf][nf][2], acc[mf][nf][3]);
            float2 q0 = *(const float2*)(R + o0);
            float2 q1 = *(const float2*)(R + o1);
            v0.x += q0.x; v0.y += q0.y;
            v1.x += q1.x; v1.y += q1.y;
            *(float2*)(C + o0) = v0;
            *(float2*)(C + o1) = v1;
        }
    }
}

// ---------------------------------------------------------------------------
// Kernel 4: V staging bf16 -> bf16 transposed [b][h][d][s]
// ---------------------------------------------------------------------------
__global__ void __launch_bounds__(256) vconv_kernel(
    const __nv_bfloat16* __restrict__ Vst, __nv_bfloat16* __restrict__ Vt)
{
    __shared__ __nv_bfloat16 ts[32][33];
    const int tx = threadIdx.x & 31, ty = threadIdx.x >> 5;   // 32x8
    const int s0  = blockIdx.x * 32;
    const int hd0 = blockIdx.y * 32;          // h*128 + d0
    const int b   = blockIdx.z;

    #pragma unroll
    for (int j = 0; j < 4; j++) {
        int r = ty + j * 8;   // s offset
        ts[r][tx] = Vst[(size_t)(b * SS + s0 + r) * DD + hd0 + tx];
    }
    __syncthreads();
    #pragma unroll
    for (int j = 0; j < 4; j++) {
        int dt = ty + j * 8;  // d offset
        Vt[((size_t)b * HH * DH + hd0 + dt) * SS + s0 + tx] = ts[tx][dt];
    }
}

// ---------------------------------------------------------------------------
// Kernel 5: flash attention on mma.sync (R13 config: 64 q-rows, 128 thr,
// cp.async double buffer, ldmatrix B-frags, V from transposed Vt).
// ---------------------------------------------------------------------------
#define AST 136
#define VST 72
#define ATTN_SMEM (2 * (64 * AST + 128 * VST) * 2)

__global__ void __launch_bounds__(128, 2) attn_mma(
    const __nv_bfloat16* __restrict__ Qb, const __nv_bfloat16* __restrict__ Kb,
    const __nv_bfloat16* __restrict__ Vt, __nv_bfloat16* __restrict__ ctx)
{
    extern __shared__ __nv_bfloat16 dsm[];
    __nv_bfloat16* KsBase = dsm;                   // 2 x 64*AST
    __nv_bfloat16* VsBase = dsm + 2 * 64 * AST;    // 2 x 128*VST

    const int tid = threadIdx.x, w = tid >> 5, lane = tid & 31;
    const int gid = lane >> 2, tid2 = lane & 3;
    const int qt = blockIdx.x, h = blockIdx.y, b = blockIdx.z;
    const int bh = b * HH + h;

    // ldmatrix lane mapping for B operands (same as GEMM)
    const int bl_row = ((lane >> 4) & 1) * 8 + (lane & 7);
    const int bl_k   = ((lane >> 3) & 1) * 8;

    const __nv_bfloat16* kgp = Kb + (size_t)bh * SS * DH;
    const __nv_bfloat16* vgp = Vt + (size_t)bh * DH * SS;

    #define ATTN_LOAD(buf, kt_) do { \
        __nv_bfloat16* Kd = KsBase + (buf) * 64 * AST; \
        __nv_bfloat16* Vd = VsBase + (buf) * 128 * VST; \
        _Pragma("unroll") \
        for (int u = 0; u < 8; u++) { \
            int f = tid + u * 128; \
            int r = f >> 4, c = (f & 15) * 8; \
            uint32_t d_ = (uint32_t)__cvta_generic_to_shared(&Kd[r * AST + c]); \
            CP_ASYNC16(d_, kgp + (size_t)((kt_) * 64 + r) * DH + c); \
        } \
        _Pragma("unroll") \
        for (int u = 0; u < 8; u++) { \
            int f = tid + u * 128; \
            int d2 = f >> 3, c = (f & 7) * 8; \
            uint32_t d_ = (uint32_t)__cvta_generic_to_shared(&Vd[d2 * VST + c]); \
            CP_ASYNC16(d_, vgp + (size_t)d2 * SS + (kt_) * 64 + c); \
        } \
        CP_COMMIT(); \
    } while (0)

    // Q fragments: 8 k-frags x 4 regs
    uint32_t qf[8][4];
    {
        const __nv_bfloat16* qp =
            Qb + ((size_t)bh * SS + qt * 64 + w * 16) * DH;
        #pragma unroll
        for (int kf = 0; kf < 8; kf++) {
            const __nv_bfloat16* p = qp + kf * 16 + tid2 * 2;
            qf[kf][0] = *(const uint32_t*)(p + (size_t)gid * DH);
            qf[kf][1] = *(const uint32_t*)(p + (size_t)(gid + 8) * DH);
            qf[kf][2] = *(const uint32_t*)(p + (size_t)gid * DH + 8);
            qf[kf][3] = *(const uint32_t*)(p + (size_t)(gid + 8) * DH + 8);
        }
    }

    float o[16][4];
    #pragma unroll
    for (int i = 0; i < 16; i++)
        #pragma unroll
        for (int q = 0; q < 4; q++) o[i][q] = 0.f;
    float m0 = -1e30f, m1 = -1e30f, l0 = 0.f, l1 = 0.f;

    ATTN_LOAD(0, 0);
    CP_WAIT0();
    __syncthreads();

    for (int kt = 0; kt < SS / 64; kt++) {
        const int cur = kt & 1;
        if (kt + 1 < SS / 64) ATTN_LOAD((kt + 1) & 1, kt + 1);

        const __nv_bfloat16* Ks = KsBase + cur * 64 * AST;
        const __nv_bfloat16* Vs = VsBase + cur * 128 * VST;

        // scores S[16 x 64] via ldmatrix B-frags
        float s[8][4];
        #pragma unroll
        for (int nf = 0; nf < 8; nf++)
            #pragma unroll
            for (int q = 0; q < 4; q++) s[nf][q] = 0.f;

        #pragma unroll
        for (int kf = 0; kf < 8; kf++) {
            #pragma unroll
            for (int np = 0; np < 4; np++) {
                uint32_t r4[4];
                uint32_t addr = (uint32_t)__cvta_generic_to_shared(
                    (void*)&Ks[(np * 16 + bl_row) * AST + kf * 16 + bl_k]);
                LDSM4(r4, addr);
                MMA16816(s[2*np],     qf[kf], r4);
                MMA16816(s[2*np + 1], qf[kf], r4 + 2);
            }
        }

        // online softmax (rows gid -> m0/l0, gid+8 -> m1/l1)
        float mx0 = -1e30f, mx1 = -1e30f;
        #pragma unroll
        for (int nf = 0; nf < 8; nf++) {
            mx0 = fmaxf(mx0, fmaxf(s[nf][0], s[nf][1]));
            mx1 = fmaxf(mx1, fmaxf(s[nf][2], s[nf][3]));
        }
        mx0 = fmaxf(mx0, __shfl_xor_sync(0xffffffffu, mx0, 1));
        mx0 = fmaxf(mx0, __shfl_xor_sync(0xffffffffu, mx0, 2));
        mx1 = fmaxf(mx1, __shfl_xor_sync(0xffffffffu, mx1, 1));
        mx1 = fmaxf(mx1, __shfl_xor_sync(0xffffffffu, mx1, 2));

        float nm0 = fmaxf(m0, mx0), nm1 = fmaxf(m1, mx1);
        float f0 = exp2_fast(m0 - nm0), f1 = exp2_fast(m1 - nm1);
        m0 = nm0; m1 = nm1;

        float sum0 = 0.f, sum1 = 0.f;
        #pragma unroll
        for (int nf = 0; nf < 8; nf++) {
            s[nf][0] = exp2_fast(s[nf][0] - m0);
            s[nf][1] = exp2_fast(s[nf][1] - m0);
            s[nf][2] = exp2_fast(s[nf][2] - m1);
            s[nf][3] = exp2_fast(s[nf][3] - m1);
            sum0 += s[nf][0] + s[nf][1];
            sum1 += s[nf][2] + s[nf][3];
        }
        sum0 += __shfl_xor_sync(0xffffffffu, sum0, 1);
        sum0 += __shfl_xor_sync(0xffffffffu, sum0, 2);
        sum1 += __shfl_xor_sync(0xffffffffu, sum1, 1);
        sum1 += __shfl_xor_sync(0xffffffffu, sum1, 2);
        l0 = l0 * f0 + sum0;
        l1 = l1 * f1 + sum1;

        #pragma unroll
        for (int nd = 0; nd < 16; nd++) {
            o[nd][0] *= f0; o[nd][1] *= f0;
            o[nd][2] *= f1; o[nd][3] *= f1;
        }

        // P @ V via ldmatrix B-frags
        #pragma unroll
        for (int kf2 = 0; kf2 < 4; kf2++) {
            uint32_t pa[4];
            pa[0] = pack_bf16x2(s[2*kf2][0],   s[2*kf2][1]);
            pa[1] = pack_bf16x2(s[2*kf2][2],   s[2*kf2][3]);
            pa[2] = pack_bf16x2(s[2*kf2+1][0], s[2*kf2+1][1]);
            pa[3] = pack_bf16x2(s[2*kf2+1][2], s[2*kf2+1][3]);
            #pragma unroll
            for (int np2 = 0; np2 < 8; np2++) {
                uint32_t r4[4];
                uint32_t addr = (uint32_t)__cvta_generic_to_shared(
                    (void*)&Vs[(np2 * 16 + bl_row) * VST + kf2 * 16 + bl_k]);
                LDSM4(r4, addr);
                MMA16816(o[2*np2],     pa, r4);
                MMA16816(o[2*np2 + 1], pa, r4 + 2);
            }
        }

        if (kt + 1 < SS / 64) CP_WAIT0();
        __syncthreads();
    }

    // epilogue: normalize, write ctx [row][h*128+d] bf16
    const float il0 = 1.f / l0, il1 = 1.f / l1;
    const size_t row0 = (size_t)(b * SS + qt * 64 + w * 16 + gid);
    __nv_bfloat16* cp0 = ctx + row0 * DD + h * DH + tid2 * 2;
    __nv_bfloat16* cp1 = cp0 + 8 * DD;
    #pragma unroll
    for (int nd = 0; nd < 16; nd++) {
        *(uint32_t*)(cp0 + nd * 8) = pack_bf16x2(o[nd][0] * il0, o[nd][1] * il0);
        *(uint32_t*)(cp1 + nd * 8) = pack_bf16x2(o[nd][2] * il1, o[nd][3] * il1);
    }
    #undef ATTN_LOAD
}

// ---------------------------------------------------------------------------
// Launch. Inputs: X, ln_w, ln_b, W_in, W_out. Output fp32.
// ---------------------------------------------------------------------------
extern "C" void kernel_launch(void* const* d_in, const int* in_sizes, int n_in,
                              void* d_out, int out_size)
{
    const float* X     = (const float*)d_in[0];
    const float* ln_w  = (const float*)d_in[1];
    const float* ln_b  = (const float*)d_in[2];
    const float* W_in  = (const float*)d_in[3];
    const float* W_out = (const float*)d_in[4];
    float*       out   = (float*)d_out;

    __nv_bfloat16 *pXn, *pWt, *pWoT, *pQb, *pKb, *pVst, *pVt, *pCtx;
    cudaGetSymbolAddress((void**)&pXn,  g_Xnb);
    cudaGetSymbolAddress((void**)&pWt,  g_Wt);
    cudaGetSymbolAddress((void**)&pWoT, g_WoT);
    cudaGetSymbolAddress((void**)&pQb,  g_Qb);
    cudaGetSymbolAddress((void**)&pKb,  g_Kb);
    cudaGetSymbolAddress((void**)&pVst, g_Vst);
    cudaGetSymbolAddress((void**)&pVt,  g_Vt);
    cudaGetSymbolAddress((void**)&pCtx, g_ctx);

    cudaFuncSetAttribute(attn_mma,
        cudaFuncAttributeMaxDynamicSharedMemorySize, ATTN_SMEM);
    cudaFuncSetAttribute(mma_gemm_qkv,
        cudaFuncAttributeMaxDynamicSharedMemorySize, GEMM_SMEM);
    cudaFuncSetAttribute(mma_gemm_out,
        cudaFuncAttributeMaxDynamicSharedMemorySize, GEMM_SMEM);

    // 0) Weight transpose -> bf16
    wsplit_kernel<<<dim3(NQKV / 32, DD / 32), 256>>>(W_in,  pWt,  NQKV);
    wsplit_kernel<<<dim3(DD   / 32, DD / 32), 256>>>(W_out, pWoT, DD);

    // 1) LayerNorm -> bf16
    ln_kernel<<<MM, 256>>>(X, ln_w, ln_b, pXn);

    // 2) QKV projection with fused RoPE + bf16 conversion (3-stage pipeline)
    mma_gemm_qkv<<<dim3(NQKV / 128, MM / 128), 128, GEMM_SMEM>>>(
        pXn, pWt, pQb, pKb, pVst);

    // 3) V transpose bf16 -> [b][h][d][s]
    vconv_kernel<<<dim3(SS / 32, HH * DH / 32, BB), 256>>>(pVst, pVt);

    // 4) Attention (R13 config: 64-q-row blocks)
    attn_mma<<<dim3(SS / 64, HH, BB), 128, ATTN_SMEM>>>(pQb, pKb, pVt, pCtx);

    // 5) Output projection + residual (3-stage pipeline)
    mma_gemm_out<<<dim3(DD / 128, MM / 128), 128, GEMM_SMEM>>>(
        pCtx, pWoT, X, out, DD);
}